// round 8
// baseline (speedup 1.0000x reference)
#include <cuda_runtime.h>

// heightfield: [16,1,512,512] f32 -> same shape.
// out[w] = 1 - clip( max_{r=1..16}( pad(row)[w+r] - r/10 ) - row[w], 0, 1 )
// Grid-stride persistent kernel, software-pipelined: prefetch next quad's five
// overlapped float4 loads while computing the current quad. Thread-local bias
// g[k] = v[k] - 0.1k. No smem, no shuffles, coalesced LDG.128/STG.128.

#define IM 512
#define NEG (-1e30f)
#define THREADS 256
#define CTAS 1184                      // 8 CTAs per SM on 148 SMs
#define NQ (4194304 / 4)               // total output quads

__device__ __forceinline__ void load5(const float* __restrict__ in, int q, float4* v) {
    const int c0 = q << 2;
    const int col = c0 & (IM - 1);
    const float* p = in + c0;
    v[0] = *reinterpret_cast<const float4*>(p);          // always in-row
    #pragma unroll
    for (int i = 1; i < 5; ++i) {
        if (col + 4 * i <= IM - 4)
            v[i] = *reinterpret_cast<const float4*>(p + 4 * i);
        else
            v[i] = make_float4(NEG, NEG, NEG, NEG);
    }
}

__device__ __forceinline__ void compute_store(float* __restrict__ out, int q,
                                              const float4* v) {
    const int c0 = q << 2;
    float g[20];
    #pragma unroll
    for (int i = 0; i < 5; ++i) {
        g[4*i+0] = v[i].x - 0.1f * (4*i+0);
        g[4*i+1] = v[i].y - 0.1f * (4*i+1);
        g[4*i+2] = v[i].z - 0.1f * (4*i+2);
        g[4*i+3] = v[i].w - 0.1f * (4*i+3);
    }
    // common max over k = 4..16
    float cm = g[4];
    #pragma unroll
    for (int k = 5; k <= 16; ++k) cm = fmaxf(cm, g[k]);

    const float a = fmaxf(g[2], g[3]);
    const float b = fmaxf(g[17], g[18]);
    const float m0 = fmaxf(cm, fmaxf(g[1], a));
    const float m1 = fmaxf(cm, fmaxf(a, g[17]));
    const float m2 = fmaxf(cm, fmaxf(g[3], b));
    const float m3 = fmaxf(cm, fmaxf(b, g[19]));

    float4 o;
    o.x = __saturatef(1.0f + (g[0] - m0));
    o.y = __saturatef(1.0f + (g[1] - m1));
    o.z = __saturatef(1.0f + (g[2] - m2));
    o.w = __saturatef(1.0f + (g[3] - m3));
    *reinterpret_cast<float4*>(out + c0) = o;
}

__global__ __launch_bounds__(THREADS) void shadow_pipe(const float* __restrict__ in,
                                                       float* __restrict__ out) {
    const int NT = CTAS * THREADS;     // 303,104 threads
    int q = blockIdx.x * THREADS + threadIdx.x;

    float4 v[5];
    load5(in, q, v);

    for (;;) {
        const int qn = q + NT;
        float4 vn[5];
        const bool more = (qn < NQ);
        if (more) load5(in, qn, vn);   // prefetch next iteration (overlaps compute)

        compute_store(out, q, v);

        if (!more) break;
        #pragma unroll
        for (int i = 0; i < 5; ++i) v[i] = vn[i];
        q = qn;
    }
}

extern "C" void kernel_launch(void* const* d_in, const int* in_sizes, int n_in,
                              void* d_out, int out_size) {
    const float* in = (const float*)d_in[0];
    float* out = (float*)d_out;
    shadow_pipe<<<CTAS, THREADS>>>(in, out);
}

// round 9
// speedup vs baseline: 1.2294x; 1.2294x over previous
#include <cuda_runtime.h>

// heightfield: [16,1,512,512] f32 -> same shape.
// out[w] = 1 - clip( max_{r=1..16}( pad(row)[w+r] - r/10 ) - row[w], 0, 1 )
// R6 structure (thread-local bias, 5 overlapped float4 loads, 4 outputs/thread)
// with ONE change: output stores use st.global.cs (evict-first streaming) to
// decouple the output writeback stream from L2 residency of the input.

#define IM 512
#define NEG (-1e30f)
#define THREADS 256

__global__ __launch_bounds__(THREADS) void shadow_cs(const float* __restrict__ in,
                                                     float* __restrict__ out) {
    const int gtid = blockIdx.x * blockDim.x + threadIdx.x;
    const int c0 = gtid << 2;              // element index (row-major)
    const int col = c0 & (IM - 1);         // column within row

    const float* p = in + c0;

    float g[20];
    // quad 0 always fully in-row (c0 <= 508)
    {
        float4 v = *reinterpret_cast<const float4*>(p);
        g[0] = v.x;                         // bias 0.0
        g[1] = v.y - 0.1f;
        g[2] = v.z - 0.2f;
        g[3] = v.w - 0.3f;
    }
    #pragma unroll
    for (int i = 1; i < 5; ++i) {
        if (col <= IM - 4 - 4 * i) {        // quad fully inside this row
            float4 v = *reinterpret_cast<const float4*>(p + 4 * i);
            g[4*i+0] = v.x - 0.1f * (4*i+0);
            g[4*i+1] = v.y - 0.1f * (4*i+1);
            g[4*i+2] = v.z - 0.1f * (4*i+2);
            g[4*i+3] = v.w - 0.1f * (4*i+3);
        } else {                            // beyond row end: never wins
            g[4*i+0] = NEG; g[4*i+1] = NEG; g[4*i+2] = NEG; g[4*i+3] = NEG;
        }
    }

    // common max over k = 4..16 (shared by all four windows)
    float cm = g[4];
    #pragma unroll
    for (int k = 5; k <= 16; ++k) cm = fmaxf(cm, g[k]);

    // window j: k in [j+1, j+16]
    const float a = fmaxf(g[2], g[3]);
    const float b = fmaxf(g[17], g[18]);
    const float m0 = fmaxf(cm, fmaxf(g[1], a));
    const float m1 = fmaxf(cm, fmaxf(a, g[17]));
    const float m2 = fmaxf(cm, fmaxf(g[3], b));
    const float m3 = fmaxf(cm, fmaxf(b, g[19]));

    float4 o;
    o.x = __saturatef(1.0f + (g[0] - m0));
    o.y = __saturatef(1.0f + (g[1] - m1));
    o.z = __saturatef(1.0f + (g[2] - m2));
    o.w = __saturatef(1.0f + (g[3] - m3));

    // evict-first streaming store
    __stcs(reinterpret_cast<float4*>(out + c0), o);
}

extern "C" void kernel_launch(void* const* d_in, const int* in_sizes, int n_in,
                              void* d_out, int out_size) {
    const float* in = (const float*)d_in[0];
    float* out = (float*)d_out;
    const int n = in_sizes[0];                 // 4,194,304
    const int threads_total = n / 4;           // 1,048,576
    shadow_cs<<<threads_total / THREADS, THREADS>>>(in, out);
}

// round 10
// speedup vs baseline: 1.2704x; 1.0333x over previous
#include <cuda_runtime.h>

// heightfield: [16,1,512,512] f32 -> same shape.
// out[w] = 1 - clip( max_{r=1..16}( pad(row)[w+r] - r/10 ) - row[w], 0, 1 )
// R9 structure (thread-local bias g[k]=v[k]-0.1k, 5 overlapped float4 loads,
// 4 outputs/thread, evict-first streaming stores) plus:
//  - 512-thread CTAs, __launch_bounds__(512,4) -> ~full occupancy
//  - warp-uniform fast path: warps not touching the row-end pad (3 of 4)
//    issue 5 unconditional loads, no predicates/selects.

#define IM 512
#define NEG (-1e30f)
#define THREADS 512

__global__ __launch_bounds__(THREADS, 4) void shadow_cs2(const float* __restrict__ in,
                                                         float* __restrict__ out) {
    const int gtid = blockIdx.x * THREADS + threadIdx.x;
    const int c0 = gtid << 2;              // element index (row-major)
    const int col = c0 & (IM - 1);         // column within row

    const float* p = in + c0;

    float g[20];
    // Warp-uniform branch: warp spans cols [wbase, wbase+124], wbase in
    // {0,128,256,384}. Only wbase==384 warps can reach the pad region.
    if (col < 384) {
        // fast path: all 5 quads unconditionally in-row (col+19 <= 402)
        #pragma unroll
        for (int i = 0; i < 5; ++i) {
            float4 v = *reinterpret_cast<const float4*>(p + 4 * i);
            g[4*i+0] = v.x - 0.1f * (4*i+0);
            g[4*i+1] = v.y - 0.1f * (4*i+1);
            g[4*i+2] = v.z - 0.1f * (4*i+2);
            g[4*i+3] = v.w - 0.1f * (4*i+3);
        }
    } else {
        // slow path: quad 0 always in-row; quads 1..4 may be past row end
        float4 v0 = *reinterpret_cast<const float4*>(p);
        g[0] = v0.x; g[1] = v0.y - 0.1f; g[2] = v0.z - 0.2f; g[3] = v0.w - 0.3f;
        #pragma unroll
        for (int i = 1; i < 5; ++i) {
            if (col + 4 * i <= IM - 4) {
                float4 v = *reinterpret_cast<const float4*>(p + 4 * i);
                g[4*i+0] = v.x - 0.1f * (4*i+0);
                g[4*i+1] = v.y - 0.1f * (4*i+1);
                g[4*i+2] = v.z - 0.1f * (4*i+2);
                g[4*i+3] = v.w - 0.1f * (4*i+3);
            } else {                       // pad: never wins the max
                g[4*i+0] = NEG; g[4*i+1] = NEG; g[4*i+2] = NEG; g[4*i+3] = NEG;
            }
        }
    }

    // common max over k = 4..16 (shared by all four windows)
    float cm = g[4];
    #pragma unroll
    for (int k = 5; k <= 16; ++k) cm = fmaxf(cm, g[k]);

    // window j: k in [j+1, j+16]
    const float a = fmaxf(g[2], g[3]);
    const float b = fmaxf(g[17], g[18]);
    const float m0 = fmaxf(cm, fmaxf(g[1], a));
    const float m1 = fmaxf(cm, fmaxf(a, g[17]));
    const float m2 = fmaxf(cm, fmaxf(g[3], b));
    const float m3 = fmaxf(cm, fmaxf(b, g[19]));

    float4 o;
    o.x = __saturatef(1.0f + (g[0] - m0));
    o.y = __saturatef(1.0f + (g[1] - m1));
    o.z = __saturatef(1.0f + (g[2] - m2));
    o.w = __saturatef(1.0f + (g[3] - m3));

    __stcs(reinterpret_cast<float4*>(out + c0), o);   // evict-first streaming store
}

extern "C" void kernel_launch(void* const* d_in, const int* in_sizes, int n_in,
                              void* d_out, int out_size) {
    const float* in = (const float*)d_in[0];
    float* out = (float*)d_out;
    const int n = in_sizes[0];                 // 4,194,304
    const int threads_total = n / 4;           // 1,048,576
    shadow_cs2<<<threads_total / THREADS, THREADS>>>(in, out);
}